// round 14
// baseline (speedup 1.0000x reference)
#include <cuda_runtime.h>

typedef unsigned long long u64;

// ---- packed f32x2 helpers (sm_100+ PTX) ----
__device__ __forceinline__ u64 pk2(float a, float b) {
    u64 r; asm("mov.b64 %0,{%1,%2};" : "=l"(r) : "f"(a), "f"(b)); return r;
}
__device__ __forceinline__ void up2(u64 v, float& a, float& b) {
    asm("mov.b64 {%0,%1},%2;" : "=f"(a), "=f"(b) : "l"(v));
}
__device__ __forceinline__ u64 swap2(u64 v) {
    float a, b; up2(v, a, b); return pk2(b, a);
}
__device__ __forceinline__ u64 f2fma(u64 a, u64 b, u64 c) {
    u64 d; asm("fma.rn.f32x2 %0,%1,%2,%3;" : "=l"(d) : "l"(a), "l"(b), "l"(c)); return d;
}
__device__ __forceinline__ u64 f2mul(u64 a, u64 b) {
    u64 d; asm("mul.rn.f32x2 %0,%1,%2;" : "=l"(d) : "l"(a), "l"(b)); return d;
}
__host__ __device__ constexpr u64 PKC(float f) {
    unsigned u = __builtin_bit_cast(unsigned, f);
    return ((u64)u << 32) | (u64)u;
}

// Tsit5 coefficients (fp32)
#define A21 0.161f
#define A31 (-0.008480655492356989f)
#define A32 0.335480655492357f
#define A41 2.8971530571054935f
#define A42 (-6.359448489975075f)
#define A43 4.3622954328695815f
#define A51 5.325864828439257f
#define A52 (-11.748883564062828f)
#define A53 7.4955393428898365f
#define A54 (-0.09249506636175525f)
#define A61 5.86145544294642f
#define A62 (-12.92096931784711f)
#define A63 8.159367898576159f
#define A64 (-0.071584973281401f)
#define A65 (-0.028269050394068383f)
#define B1 0.09646076681806523f
#define B2 0.01f
#define B3 0.4798896504144996f
#define B4 1.379008574103742f
#define B5 (-3.290069515436081f)
#define B6 2.324710524099774f
#define E1 (-0.001780011052225777f)
#define E2 (-0.0008164344596567469f)
#define E3 0.007880878010261995f
#define E4 (-0.1447110071732629f)
#define E5 0.5823571654525552f
#define E6 (-0.45808210592918697f)
#define E7 0.015151515151515152f

#define ATOL 1e-8f
#define RTOL 1e-4f
#define PRED_LEN 32
#define MAX_STEPS 12

// Log-domain controller (see R13): accept iff max lane log-ratio <= log2(2),
// bits(fac) = FAC1 - 0.2*lmax.
#define FAC1 1065755873
#define FAC_FIFTH 858993459   // round(0.2 * 2^32)
#define L_TWO (1 << 23)

// Fully-packed RHS: for y=(S,I), SI = y*swap(y) = (S*I, S*I);
// k = gmv*y + bnv*SI = (-bN*SI, bN*SI - gm*I) = (dS, dI).
#define PRHSP(yv, kout)                           \
    {                                             \
        u64 _sw = swap2(yv);                      \
        u64 _si = f2mul((yv), _sw);               \
        kout = f2fma(gmv, (yv), f2mul(bnv, _si)); \
    }

__global__ void __launch_bounds__(32) sird_kernel(
    const float* __restrict__ x,          // [B,3] beta,gamma,mu
    const float* __restrict__ gp,         // [B,1]
    const float* __restrict__ population, // [B]
    float* __restrict__ out,              // [B,32,4]
    int B)
{
    int b = blockIdx.x * blockDim.x + threadIdx.x;
    if (b >= B) return;

    const float beta  = x[3 * b + 0];
    const float gamma = x[3 * b + 1];
    const float mu    = x[3 * b + 2];
    const float N     = population[b];
    const float bN    = beta / N;
    const float gm    = gamma + mu;

    const u64 bnv = pk2(-bN, bN);
    const u64 gmv = pk2(0.0f, -gm);

    float S = gp[b] - 100.0f;
    float I = 100.0f;
    float R = 0.0f;
    float D = 0.0f;

    float4* orow = reinterpret_cast<float4*>(out + (size_t)b * (PRED_LEN * 4));
    orow[0] = make_float4(S, I, R, D);

    float dt = 0.05f;
    const float tstep = 32.0f / 31.0f;

    // FSAL: k1 = RHS(y) carried across steps (autonomous RHS).
    u64 k1;
    {
        u64 y0 = pk2(S, I);
        PRHSP(y0, k1);
    }

    for (int iv = 0; iv < PRED_LEN - 1; ++iv) {
        const float t1 = (float)(iv + 1) * tstep;
        float t = (float)iv * tstep;

        for (int s = 0; s < MAX_STEPS; ++s) {
            float h = fmaxf(fminf(dt, t1 - t), 1e-9f);
            u64 h2 = pk2(h, h);
            u64 y2 = pk2(S, I);

            u64 a2v = f2fma(h2, f2mul(PKC(A21), k1), y2);
            u64 k2; PRHSP(a2v, k2);

            u64 a3v = f2fma(h2, f2fma(PKC(A32), k2, f2mul(PKC(A31), k1)), y2);
            u64 k3; PRHSP(a3v, k3);

            u64 a4v = f2fma(h2, f2fma(PKC(A43), k3, f2fma(PKC(A42), k2, f2mul(PKC(A41), k1))), y2);
            u64 k4; PRHSP(a4v, k4);

            u64 a5v = f2fma(h2, f2fma(PKC(A54), k4, f2fma(PKC(A53), k3, f2fma(PKC(A52), k2, f2mul(PKC(A51), k1)))), y2);
            u64 k5; PRHSP(a5v, k5);

            u64 a6v = f2fma(h2, f2fma(PKC(A65), k5, f2fma(PKC(A64), k4, f2fma(PKC(A63), k3, f2fma(PKC(A62), k2, f2mul(PKC(A61), k1))))), y2);
            u64 k6; PRHSP(a6v, k6);

            u64 ny2 = f2fma(h2,
                f2fma(PKC(B6), k6, f2fma(PKC(B5), k5, f2fma(PKC(B4), k4,
                    f2fma(PKC(B3), k3, f2fma(PKC(B2), k2, f2mul(PKC(B1), k1)))))), y2);

            u64 k7; PRHSP(ny2, k7);

            // packed error estimate for (S, I)
            u64 e2 = f2mul(h2,
                f2fma(PKC(E7), k7, f2fma(PKC(E6), k6, f2fma(PKC(E5), k5,
                    f2fma(PKC(E4), k4, f2fma(PKC(E3), k3, f2fma(PKC(E2), k2, f2mul(PKC(E1), k1))))))));

            // I-stage sums for R/D as packed chains over stage vectors
            // (lane1 = sum of coeff * I_j ; lane0 garbage, ignored)
            u64 SB2 = f2fma(PKC(B6), a6v, f2fma(PKC(B5), a5v, f2fma(PKC(B4), a4v,
                        f2fma(PKC(B3), a3v, f2fma(PKC(B2), a2v, f2mul(PKC(B1), y2))))));
            u64 SE2 = f2fma(PKC(E7), ny2, f2fma(PKC(E6), a6v, f2fma(PKC(E5), a5v,
                        f2fma(PKC(E4), a4v, f2fma(PKC(E3), a3v, f2fma(PKC(E2), a2v, f2mul(PKC(E1), y2)))))));

            float nS, nI, es, ei, dumb, SB, dume, SE;
            up2(ny2, nS, nI);
            up2(e2, es, ei);
            up2(SB2, dumb, SB);
            up2(SE2, dume, SE);

            const float hg = h * gamma;
            const float hm = h * mu;
            float nR = fmaf(hg, SB, R);
            float nD = fmaf(hm, SB, D);
            (void)SE;  // R/D error components dropped from accept norm (non-binding)

            float ts_ = fmaf(RTOL, fmaxf(fabsf(S), fabsf(nS)), ATOL);
            float ti_ = fmaf(RTOL, fmaxf(fabsf(I), fabsf(nI)), ATOL);

            // ---- log-domain controller (divide-free) ----
            int lrs = (int)(__float_as_uint(es) & 0x7fffffffu) - (int)__float_as_uint(ts_);
            int lri = (int)(__float_as_uint(ei) & 0x7fffffffu) - (int)__float_as_uint(ti_);
            int lmax = max(lrs, lri);

            int facb = FAC1 - __mulhi(lmax, FAC_FIFTH);
            float fac = fminf(fmaxf(__int_as_float(facb), 0.2f), 10.0f);
            dt = h * fac;

            if (lmax <= L_TWO) {
                t += h;
                S = nS; I = nI; R = nR; D = nD;
                k1 = k7;  // FSAL
            }
            if (t >= t1 - 1e-6f) break;
        }

        orow[iv + 1] = make_float4(S, I, R, D);
    }
}

extern "C" void kernel_launch(void* const* d_in, const int* in_sizes, int n_in,
                              void* d_out, int out_size)
{
    const float* x   = (const float*)d_in[0];
    const float* gp  = (const float*)d_in[1];
    const float* pop = (const float*)d_in[2];
    float* out = (float*)d_out;
    int B = in_sizes[2];  // population has B elements

    int threads = 32;
    int blocks = (B + threads - 1) / threads;
    sird_kernel<<<blocks, threads>>>(x, gp, pop, out, B);
}

// round 15
// speedup vs baseline: 1.0101x; 1.0101x over previous
#include <cuda_runtime.h>

typedef unsigned long long u64;

// ---- packed f32x2 helpers (sm_100+ PTX) ----
__device__ __forceinline__ u64 pk2(float a, float b) {
    u64 r; asm("mov.b64 %0,{%1,%2};" : "=l"(r) : "f"(a), "f"(b)); return r;
}
__device__ __forceinline__ void up2(u64 v, float& a, float& b) {
    asm("mov.b64 {%0,%1},%2;" : "=f"(a), "=f"(b) : "l"(v));
}
__device__ __forceinline__ u64 swap2(u64 v) {
    float a, b; up2(v, a, b); return pk2(b, a);
}
__device__ __forceinline__ u64 f2fma(u64 a, u64 b, u64 c) {
    u64 d; asm("fma.rn.f32x2 %0,%1,%2,%3;" : "=l"(d) : "l"(a), "l"(b), "l"(c)); return d;
}
__device__ __forceinline__ u64 f2mul(u64 a, u64 b) {
    u64 d; asm("mul.rn.f32x2 %0,%1,%2;" : "=l"(d) : "l"(a), "l"(b)); return d;
}
__host__ __device__ constexpr u64 PKC(float f) {
    unsigned u = __builtin_bit_cast(unsigned, f);
    return ((u64)u << 32) | (u64)u;
}

// Tsit5 coefficients (fp32)
#define A21 0.161f
#define A31 (-0.008480655492356989f)
#define A32 0.335480655492357f
#define A41 2.8971530571054935f
#define A42 (-6.359448489975075f)
#define A43 4.3622954328695815f
#define A51 5.325864828439257f
#define A52 (-11.748883564062828f)
#define A53 7.4955393428898365f
#define A54 (-0.09249506636175525f)
#define A61 5.86145544294642f
#define A62 (-12.92096931784711f)
#define A63 8.159367898576159f
#define A64 (-0.071584973281401f)
#define A65 (-0.028269050394068383f)
#define B1 0.09646076681806523f
#define B2 0.01f
#define B3 0.4798896504144996f
#define B4 1.379008574103742f
#define B5 (-3.290069515436081f)
#define B6 2.324710524099774f
#define E1 (-0.001780011052225777f)
#define E2 (-0.0008164344596567469f)
#define E3 0.007880878010261995f
#define E4 (-0.1447110071732629f)
#define E5 0.5823571654525552f
#define E6 (-0.45808210592918697f)
#define E7 0.015151515151515152f

#define ATOL 1e-8f
#define RTOL 1e-4f
#define PRED_LEN 32
#define MAX_STEPS 12

// Log-domain controller (see R13): accept iff max lane log-ratio <= log2(2),
// bits(fac) = FAC1 - 0.2*lmax.
#define FAC1 1065755873
#define FAC_FIFTH 858993459   // round(0.2 * 2^32)
#define L_TWO (1 << 23)

// Fully-packed RHS: for y=(S,I), SI = y*swap(y) = (S*I, S*I);
// k = gmv*y + bnv*SI = (-bN*SI, bN*SI - gm*I) = (dS, dI).
#define PRHSP(yv, kout)                           \
    {                                             \
        u64 _sw = swap2(yv);                      \
        u64 _si = f2mul((yv), _sw);               \
        kout = f2fma(gmv, (yv), f2mul(bnv, _si)); \
    }

__global__ void __launch_bounds__(32) sird_kernel(
    const float* __restrict__ x,          // [B,3] beta,gamma,mu
    const float* __restrict__ gp,         // [B,1]
    const float* __restrict__ population, // [B]
    float* __restrict__ out,              // [B,32,4]
    int B)
{
    int b = blockIdx.x * blockDim.x + threadIdx.x;
    if (b >= B) return;

    const float beta  = x[3 * b + 0];
    const float gamma = x[3 * b + 1];
    const float mu    = x[3 * b + 2];
    const float N     = population[b];
    const float bN    = beta / N;
    const float gm    = gamma + mu;

    const u64 bnv = pk2(-bN, bN);
    const u64 gmv = pk2(0.0f, -gm);

    float S = gp[b] - 100.0f;
    float I = 100.0f;
    float R = 0.0f;
    float D = 0.0f;

    float4* orow = reinterpret_cast<float4*>(out + (size_t)b * (PRED_LEN * 4));
    orow[0] = make_float4(S, I, R, D);

    float dt = 0.05f;
    const float tstep = 32.0f / 31.0f;

    // FSAL: k1 = RHS(y) carried across steps (autonomous RHS).
    u64 k1;
    {
        u64 y0 = pk2(S, I);
        PRHSP(y0, k1);
    }

    for (int iv = 0; iv < PRED_LEN - 1; ++iv) {
        const float t1 = (float)(iv + 1) * tstep;
        float t = (float)iv * tstep;

        for (int s = 0; s < MAX_STEPS; ++s) {
            const float rem = t1 - t;
            const bool capped = dt > rem;          // step limited by interval end
            float h = fmaxf(fminf(dt, rem), 1e-9f);
            u64 h2 = pk2(h, h);
            u64 y2 = pk2(S, I);

            u64 a2v = f2fma(h2, f2mul(PKC(A21), k1), y2);
            u64 k2; PRHSP(a2v, k2);

            u64 a3v = f2fma(h2, f2fma(PKC(A32), k2, f2mul(PKC(A31), k1)), y2);
            u64 k3; PRHSP(a3v, k3);

            u64 a4v = f2fma(h2, f2fma(PKC(A43), k3, f2fma(PKC(A42), k2, f2mul(PKC(A41), k1))), y2);
            u64 k4; PRHSP(a4v, k4);

            u64 a5v = f2fma(h2, f2fma(PKC(A54), k4, f2fma(PKC(A53), k3, f2fma(PKC(A52), k2, f2mul(PKC(A51), k1)))), y2);
            u64 k5; PRHSP(a5v, k5);

            u64 a6v = f2fma(h2, f2fma(PKC(A65), k5, f2fma(PKC(A64), k4, f2fma(PKC(A63), k3, f2fma(PKC(A62), k2, f2mul(PKC(A61), k1))))), y2);
            u64 k6; PRHSP(a6v, k6);

            u64 ny2 = f2fma(h2,
                f2fma(PKC(B6), k6, f2fma(PKC(B5), k5, f2fma(PKC(B4), k4,
                    f2fma(PKC(B3), k3, f2fma(PKC(B2), k2, f2mul(PKC(B1), k1)))))), y2);

            u64 k7; PRHSP(ny2, k7);

            // packed error estimate for (S, I)
            u64 e2 = f2mul(h2,
                f2fma(PKC(E7), k7, f2fma(PKC(E6), k6, f2fma(PKC(E5), k5,
                    f2fma(PKC(E4), k4, f2fma(PKC(E3), k3, f2fma(PKC(E2), k2, f2mul(PKC(E1), k1))))))));

            // I-stage B-sum for R/D as a packed chain over stage vectors
            // (lane1 = sum of B_j * I_j ; lane0 garbage, ignored)
            u64 SB2 = f2fma(PKC(B6), a6v, f2fma(PKC(B5), a5v, f2fma(PKC(B4), a4v,
                        f2fma(PKC(B3), a3v, f2fma(PKC(B2), a2v, f2mul(PKC(B1), y2))))));

            float nS, nI, es, ei, dumb, SB;
            up2(ny2, nS, nI);
            up2(e2, es, ei);
            up2(SB2, dumb, SB);

            const float hg = h * gamma;
            const float hm = h * mu;
            float nR = fmaf(hg, SB, R);
            float nD = fmaf(hm, SB, D);

            float ts_ = fmaf(RTOL, fmaxf(fabsf(S), fabsf(nS)), ATOL);
            float ti_ = fmaf(RTOL, fmaxf(fabsf(I), fabsf(nI)), ATOL);

            // ---- log-domain controller (divide-free) ----
            int lrs = (int)(__float_as_uint(es) & 0x7fffffffu) - (int)__float_as_uint(ts_);
            int lri = (int)(__float_as_uint(ei) & 0x7fffffffu) - (int)__float_as_uint(ti_);
            int lmax = max(lrs, lri);

            int facb = FAC1 - __mulhi(lmax, FAC_FIFTH);
            float fac = fminf(fmaxf(__int_as_float(facb), 0.2f), 10.0f);
            float dtn = h * fac;
            // Anti-collapse: a boundary-capped step must not shrink the natural
            // step size (controller-only change; accept test unchanged).
            dt = capped ? fmaxf(dt, dtn) : dtn;

            if (lmax <= L_TWO) {
                t += h;
                S = nS; I = nI; R = nR; D = nD;
                k1 = k7;  // FSAL
            }
            if (t >= t1 - 1e-6f) break;
        }

        orow[iv + 1] = make_float4(S, I, R, D);
    }
}

extern "C" void kernel_launch(void* const* d_in, const int* in_sizes, int n_in,
                              void* d_out, int out_size)
{
    const float* x   = (const float*)d_in[0];
    const float* gp  = (const float*)d_in[1];
    const float* pop = (const float*)d_in[2];
    float* out = (float*)d_out;
    int B = in_sizes[2];  // population has B elements

    int threads = 32;
    int blocks = (B + threads - 1) / threads;
    sird_kernel<<<blocks, threads>>>(x, gp, pop, out, B);
}